// round 3
// baseline (speedup 1.0000x reference)
#include <cuda_runtime.h>
#include <math.h>

// Problem constants
#define B_  10
#define T_  2048
#define I_  128
#define H_  256
#define L_  6
#define G4  (4 * H_)      // 1024 gate rows per layer

// Kernel config
#define NBLK     24        // blocks per layer (6*24 = 144 <= 148 SMs, co-resident)
#define THREADS  512
#define KSTRIDE  524       // padded row stride (floats)
#define ROWS_MAX 44        // 4 * ceil(256/24)
#define JC_MAX   11

// Scratch (device globals: allocation-free contract)
__device__ float g_hseq[(size_t)L_ * (T_ + 1) * B_ * H_];
__device__ int   g_prog[L_ * NBLK * 32];   // per-block progress, 128B padded

__global__ void lstm_init_kernel(const float* __restrict__ h0) {
    int tid = blockIdx.x * blockDim.x + threadIdx.x;
    if (tid < L_ * B_ * H_) {
        int l = tid / (B_ * H_);
        int rem = tid - l * (B_ * H_);
        g_hseq[((size_t)l * (T_ + 1)) * B_ * H_ + rem] = h0[tid];
    }
    if (tid < L_ * NBLK * 32) {
        g_prog[tid] = 0;
    }
}

__device__ __forceinline__ float sigmoidf_fast(float x) {
    return 1.0f / (1.0f + __expf(-x));
}
__device__ __forceinline__ float tanhf_fast(float x) {
    // tanh(x) = 1 - 2/(exp(2x)+1); __expf saturates cleanly for large |x|
    return 1.0f - 2.0f / (__expf(2.0f * x) + 1.0f);
}

__global__ void __launch_bounds__(THREADS, 1)
lstm_pipeline_kernel(const float* __restrict__ x,
                     const float* __restrict__ c0,
                     const float* __restrict__ Wih0,
                     const float* __restrict__ Wih,   // [L-1][4H][H]
                     const float* __restrict__ Whh,   // [L][4H][H]
                     const float* __restrict__ bih,   // [L][4H]
                     const float* __restrict__ bhh,   // [L][4H]
                     float* __restrict__ out)         // [L][B][H]
{
    extern __shared__ float sm[];

    const int l     = blockIdx.x / NBLK;
    const int p     = blockIdx.x % NBLK;
    const int jbase = (p * H_) / NBLK;
    const int jend  = ((p + 1) * H_) / NBLK;
    const int jc    = jend - jbase;     // 10 or 11
    const int rows  = 4 * jc;           // gate rows owned by this block
    const int KIN   = (l == 0) ? I_ : H_;
    const int KTOT  = KIN + H_;
    const int tid   = threadIdx.x;

    // smem partition
    float* Wsm  = sm;                               // ROWS_MAX * KSTRIDE
    float* vbuf = Wsm  + ROWS_MAX * KSTRIDE;        // B * KSTRIDE  ([input | h_prev])
    float* acts = vbuf + B_ * KSTRIDE;              // ROWS_MAX * B
    float* csm  = acts + ROWS_MAX * B_;             // JC_MAX * B
    float* bsm  = csm  + JC_MAX * B_;               // ROWS_MAX

    // ---- load weights once (combined [Wih_row | Whh_row]) ----
    for (int e = tid; e < rows * KTOT; e += THREADS) {
        int r = e / KTOT;
        int k = e - r * KTOT;
        int gate = r / jc;
        int jl   = r - gate * jc;
        int g    = gate * H_ + jbase + jl;
        float w;
        if (k < KIN) {
            w = (l == 0) ? Wih0[(size_t)g * I_ + k]
                         : Wih[((size_t)(l - 1) * G4 + g) * H_ + k];
        } else {
            w = Whh[((size_t)l * G4 + g) * H_ + (k - KIN)];
        }
        Wsm[r * KSTRIDE + k] = w;
    }
    for (int r = tid; r < rows; r += THREADS) {
        int gate = r / jc;
        int jl   = r - gate * jc;
        int g    = gate * H_ + jbase + jl;
        bsm[r] = bih[l * G4 + g] + bhh[l * G4 + g];
    }
    for (int e = tid; e < jc * B_; e += THREADS) {
        int jl = e / B_;
        int b  = e - jl * B_;
        csm[e] = c0[((size_t)l * B_ + b) * H_ + jbase + jl];
    }
    __syncthreads();

    const int ntasks = rows * B_;       // 400 or 440 (< THREADS)
    // per-thread GEMM assignment (clamped for idle threads)
    const int task = (tid < ntasks) ? tid : 0;
    const int rr   = task / B_;
    const int bb   = task - rr * B_;

    volatile int* prog = g_prog;

    for (int t = 0; t < T_; t++) {
        // ---- wait: two dependency sets polled by two warps, lanes in parallel ----
        if (tid < 32) {
            if (tid < NBLK) {
                volatile int* f = &prog[(l * NBLK + tid) * 32];
                while (*f < t) { }
            }
            __syncwarp();
            __threadfence();
        } else if (tid < 64) {
            if (l > 0 && tid - 32 < NBLK) {
                volatile int* f = &prog[((l - 1) * NBLK + (tid - 32)) * 32];
                while (*f < t + 1) { }
            }
            __syncwarp();
            __threadfence();
        }
        __syncthreads();

        // ---- build v = [input | h_prev] in smem ----
        {
            const float4* hp = (const float4*)(g_hseq +
                ((size_t)(l * (T_ + 1) + t)) * B_ * H_);
            for (int e = tid; e < B_ * (H_ / 4); e += THREADS) {
                int b  = e / (H_ / 4);
                int k4 = e - b * (H_ / 4);
                ((float4*)(vbuf + b * KSTRIDE + KIN))[k4] = hp[b * (H_ / 4) + k4];
            }
            if (l == 0) {
                const float4* xp = (const float4*)x;
                for (int e = tid; e < B_ * (I_ / 4); e += THREADS) {
                    int b  = e / (I_ / 4);
                    int k4 = e - b * (I_ / 4);
                    ((float4*)(vbuf + b * KSTRIDE))[k4] =
                        xp[((size_t)b * T_ + t) * (I_ / 4) + k4];
                }
            } else {
                const float4* ip = (const float4*)(g_hseq +
                    ((size_t)((l - 1) * (T_ + 1) + t + 1)) * B_ * H_);
                for (int e = tid; e < B_ * (H_ / 4); e += THREADS) {
                    int b  = e / (H_ / 4);
                    int k4 = e - b * (H_ / 4);
                    ((float4*)(vbuf + b * KSTRIDE))[k4] = ip[b * (H_ / 4) + k4];
                }
            }
        }
        __syncthreads();

        // ---- gate pre-activations: one row per thread, 2 indep accumulators ----
        {
            const float4* wr = (const float4*)(Wsm + rr * KSTRIDE);
            const float4* vb = (const float4*)(vbuf + bb * KSTRIDE);
            float a0 = 0.f, a1 = 0.f;
            const int n4 = KTOT >> 2;             // 96 or 128, even
            #pragma unroll 8
            for (int k4 = 0; k4 < n4; k4 += 2) {
                float4 w0 = wr[k4];
                float4 v0 = vb[k4];
                float4 w1 = wr[k4 + 1];
                float4 v1 = vb[k4 + 1];
                a0 = fmaf(w0.x, v0.x, a0);
                a0 = fmaf(w0.y, v0.y, a0);
                a0 = fmaf(w0.z, v0.z, a0);
                a0 = fmaf(w0.w, v0.w, a0);
                a1 = fmaf(w1.x, v1.x, a1);
                a1 = fmaf(w1.y, v1.y, a1);
                a1 = fmaf(w1.z, v1.z, a1);
                a1 = fmaf(w1.w, v1.w, a1);
            }
            if (tid < ntasks) acts[task] = a0 + a1 + bsm[rr];
        }
        __syncthreads();

        // ---- pointwise LSTM cell + publish h slice ----
        float* hout = g_hseq + ((size_t)(l * (T_ + 1) + t + 1)) * B_ * H_;
        if (tid < jc * B_) {
            int e  = tid;
            int jl = e / B_;
            int b  = e - jl * B_;
            float ai = acts[(0 * jc + jl) * B_ + b];
            float af = acts[(1 * jc + jl) * B_ + b];
            float ag = acts[(2 * jc + jl) * B_ + b];
            float ao = acts[(3 * jc + jl) * B_ + b];
            float ig = sigmoidf_fast(ai);
            float fg = sigmoidf_fast(af);
            float gg = tanhf_fast(ag);
            float og = sigmoidf_fast(ao);
            float c  = fmaf(fg, csm[e], ig * gg);
            csm[e] = c;
            hout[(size_t)b * H_ + jbase + jl] = og * tanhf_fast(c);
        }
        __syncthreads();
        if (tid == 0) {
            __threadfence();
            prog[(l * NBLK + p) * 32] = t + 1;
        }
    }

    // ---- final cell states -> out[L][B][H] ----
    if (tid < jc * B_) {
        int jl = tid / B_;
        int b  = tid - jl * B_;
        out[((size_t)l * B_ + b) * H_ + jbase + jl] = csm[tid];
    }
}

#define SMEM_FLOATS (ROWS_MAX * KSTRIDE + B_ * KSTRIDE + ROWS_MAX * B_ + JC_MAX * B_ + ROWS_MAX)
#define SMEM_BYTES  (SMEM_FLOATS * (int)sizeof(float))

extern "C" void kernel_launch(void* const* d_in, const int* in_sizes, int n_in,
                              void* d_out, int out_size) {
    const float* x    = (const float*)d_in[0];
    const float* h0   = (const float*)d_in[1];
    const float* c0   = (const float*)d_in[2];
    const float* Wih0 = (const float*)d_in[3];
    const float* Wih  = (const float*)d_in[4];
    const float* Whh  = (const float*)d_in[5];
    const float* bih  = (const float*)d_in[6];
    const float* bhh  = (const float*)d_in[7];
    float* out = (float*)d_out;

    cudaFuncSetAttribute(lstm_pipeline_kernel,
                         cudaFuncAttributeMaxDynamicSharedMemorySize, SMEM_BYTES);

    lstm_init_kernel<<<64, 256>>>(h0);
    lstm_pipeline_kernel<<<L_ * NBLK, THREADS, SMEM_BYTES>>>(
        x, c0, Wih0, Wih, Whh, bih, bhh, out);
}

// round 4
// speedup vs baseline: 1.7126x; 1.7126x over previous
#include <cuda_runtime.h>
#include <math.h>

// Problem constants
#define B_  10
#define T_  2048
#define I_  128
#define H_  256
#define L_  6
#define G4  (4 * H_)      // 1024 gate rows per layer

// Kernel config
#define NBLK     24        // blocks per layer (6*24 = 144 <= 148 SMs, co-resident)
#define THREADS  448
#define ROWS_MAX 44        // 4 * ceil(256/24)
#define JC_MAX   11
#define KC       64        // k-chunk per thread (16 float4 registers)
#define NKC_MAX  8         // 512 / 64
#define KSTRIDE  520       // vbuf row stride (floats)

// Scratch (device globals: allocation-free contract)
__device__ float g_hseq[(size_t)L_ * (T_ + 1) * B_ * H_];
__device__ int   g_prog[L_ * NBLK * 32];   // per-block progress, 128B padded

__global__ void lstm_init_kernel(const float* __restrict__ h0) {
    int tid = blockIdx.x * blockDim.x + threadIdx.x;
    if (tid < L_ * B_ * H_) {
        int l = tid / (B_ * H_);
        int rem = tid - l * (B_ * H_);
        g_hseq[((size_t)l * (T_ + 1)) * B_ * H_ + rem] = h0[tid];
    }
    if (tid < L_ * NBLK * 32) {
        g_prog[tid] = 0;
    }
}

__device__ __forceinline__ float sigmoidf_fast(float x) {
    return 1.0f / (1.0f + __expf(-x));
}
__device__ __forceinline__ float tanhf_fast(float x) {
    return 1.0f - 2.0f / (__expf(2.0f * x) + 1.0f);
}

__global__ void __launch_bounds__(THREADS, 1)
lstm_pipeline_kernel(const float* __restrict__ x,
                     const float* __restrict__ c0,
                     const float* __restrict__ Wih0,
                     const float* __restrict__ Wih,   // [L-1][4H][H]
                     const float* __restrict__ Whh,   // [L][4H][H]
                     const float* __restrict__ bih,   // [L][4H]
                     const float* __restrict__ bhh,   // [L][4H]
                     float* __restrict__ out)         // [L][B][H]
{
    __shared__ float vbuf[B_ * KSTRIDE];                 // [input | h_prev]
    __shared__ float psum[ROWS_MAX * B_ * NKC_MAX];      // partials [r][b][kc]
    __shared__ float csm[JC_MAX * B_];
    __shared__ float bsm[ROWS_MAX];

    const int l     = blockIdx.x / NBLK;
    const int p     = blockIdx.x % NBLK;
    const int jbase = (p * H_) / NBLK;
    const int jend  = ((p + 1) * H_) / NBLK;
    const int jc    = jend - jbase;     // 10 or 11
    const int rows  = 4 * jc;           // gate rows owned by this block
    const int KIN   = (l == 0) ? I_ : H_;
    const int KTOT  = KIN + H_;
    const int nkc   = KTOT / KC;        // 6 or 8
    const int tid   = threadIdx.x;

    // ---- GEMM task: thread = (kc, r); r fastest so warps share kc (v broadcast)
    const int rr = tid % ROWS_MAX;
    const int kc = tid / ROWS_MAX;
    const bool gemm_active = (rr < rows) && (kc < nkc);

    // ---- load this thread's 64 weights into registers (held for all steps) ----
    float4 wreg[KC / 4];
    if (gemm_active) {
        const int gate = rr / jc;
        const int jl   = rr - gate * jc;
        const int g    = gate * H_ + jbase + jl;
        const int k0   = kc * KC;
        const float4* src;
        if (k0 < KIN) {   // chunk fully inside Wih (KC=64 aligns with KIN=128/256)
            const float* wp = (l == 0) ? (Wih0 + (size_t)g * I_ + k0)
                                       : (Wih + ((size_t)(l - 1) * G4 + g) * H_ + k0);
            src = (const float4*)wp;
        } else {          // chunk fully inside Whh
            src = (const float4*)(Whh + ((size_t)l * G4 + g) * H_ + (k0 - KIN));
        }
        #pragma unroll
        for (int i = 0; i < KC / 4; i++) wreg[i] = src[i];
    } else {
        #pragma unroll
        for (int i = 0; i < KC / 4; i++) wreg[i] = make_float4(0.f, 0.f, 0.f, 0.f);
    }

    // ---- biases, initial cell state ----
    for (int r = tid; r < rows; r += THREADS) {
        int gate = r / jc;
        int jl   = r - gate * jc;
        int g    = gate * H_ + jbase + jl;
        bsm[r] = bih[l * G4 + g] + bhh[l * G4 + g];
    }
    for (int e = tid; e < jc * B_; e += THREADS) {
        int jl = e / B_;
        int b  = e - jl * B_;
        csm[e] = c0[((size_t)l * B_ + b) * H_ + jbase + jl];
    }
    __syncthreads();

    volatile int* prog = g_prog;

    for (int t = 0; t < T_; t++) {
        // ---- wait: two dependency sets polled by two warps, one flag per lane ----
        if (tid < 32) {
            if (tid < NBLK) {
                volatile int* f = &prog[(l * NBLK + tid) * 32];
                while (*f < t) { }
            }
            __syncwarp();
            __threadfence();
        } else if (tid < 64) {
            if (l > 0 && tid - 32 < NBLK) {
                volatile int* f = &prog[((l - 1) * NBLK + (tid - 32)) * 32];
                while (*f < t + 1) { }
            }
            __syncwarp();
            __threadfence();
        }
        __syncthreads();

        // ---- build v = [input | h_prev] in smem ----
        {
            const float4* hp = (const float4*)(g_hseq +
                ((size_t)(l * (T_ + 1) + t)) * B_ * H_);
            for (int e = tid; e < B_ * (H_ / 4); e += THREADS) {
                int b  = e / (H_ / 4);
                int k4 = e - b * (H_ / 4);
                ((float4*)(vbuf + b * KSTRIDE + KIN))[k4] = hp[b * (H_ / 4) + k4];
            }
            if (l == 0) {
                const float4* xp = (const float4*)x;
                for (int e = tid; e < B_ * (I_ / 4); e += THREADS) {
                    int b  = e / (I_ / 4);
                    int k4 = e - b * (I_ / 4);
                    ((float4*)(vbuf + b * KSTRIDE))[k4] =
                        xp[((size_t)b * T_ + t) * (I_ / 4) + k4];
                }
            } else {
                const float4* ip = (const float4*)(g_hseq +
                    ((size_t)((l - 1) * (T_ + 1) + t + 1)) * B_ * H_);
                for (int e = tid; e < B_ * (H_ / 4); e += THREADS) {
                    int b  = e / (H_ / 4);
                    int k4 = e - b * (H_ / 4);
                    ((float4*)(vbuf + b * KSTRIDE))[k4] = ip[b * (H_ / 4) + k4];
                }
            }
        }
        __syncthreads();

        // ---- GEMM partials: weights from registers, v broadcast from smem ----
        if (gemm_active) {
            float acc[B_];
            #pragma unroll
            for (int b = 0; b < B_; b++) acc[b] = 0.f;
            const float* vb0 = vbuf + kc * KC;
            #pragma unroll
            for (int k4 = 0; k4 < KC / 4; k4++) {
                const float4 w = wreg[k4];
                #pragma unroll
                for (int b = 0; b < B_; b++) {
                    const float4 v = *(const float4*)(vb0 + b * KSTRIDE + k4 * 4);
                    acc[b] = fmaf(w.x, v.x, acc[b]);
                    acc[b] = fmaf(w.y, v.y, acc[b]);
                    acc[b] = fmaf(w.z, v.z, acc[b]);
                    acc[b] = fmaf(w.w, v.w, acc[b]);
                }
            }
            float* po = psum + (rr * B_) * NKC_MAX + kc;
            #pragma unroll
            for (int b = 0; b < B_; b++) {
                po[b * NKC_MAX] = acc[b];
            }
        }
        __syncthreads();

        // ---- fused reduce + LSTM cell + publish h slice (110 threads) ----
        float* hout = g_hseq + ((size_t)(l * (T_ + 1) + t + 1)) * B_ * H_;
        if (tid < jc * B_) {
            const int jl = tid / B_;
            const int b  = tid - jl * B_;
            float gsum[4];
            #pragma unroll
            for (int gate = 0; gate < 4; gate++) {
                const int r = gate * jc + jl;
                const float* pp = psum + (r * B_ + b) * NKC_MAX;
                float s = bsm[r];
                for (int k = 0; k < nkc; k++) s += pp[k];
                gsum[gate] = s;
            }
            float ig = sigmoidf_fast(gsum[0]);
            float fg = sigmoidf_fast(gsum[1]);
            float gg = tanhf_fast(gsum[2]);
            float og = sigmoidf_fast(gsum[3]);
            float c  = fmaf(fg, csm[tid], ig * gg);
            csm[tid] = c;
            hout[(size_t)b * H_ + jbase + jl] = og * tanhf_fast(c);
        }
        __syncthreads();
        if (tid == 0) {
            __threadfence();
            prog[(l * NBLK + p) * 32] = t + 1;
        }
    }

    // ---- final cell states -> out[L][B][H] ----
    if (tid < jc * B_) {
        int jl = tid / B_;
        int b  = tid - jl * B_;
        out[((size_t)l * B_ + b) * H_ + jbase + jl] = csm[tid];
    }
}

extern "C" void kernel_launch(void* const* d_in, const int* in_sizes, int n_in,
                              void* d_out, int out_size) {
    const float* x    = (const float*)d_in[0];
    const float* h0   = (const float*)d_in[1];
    const float* c0   = (const float*)d_in[2];
    const float* Wih0 = (const float*)d_in[3];
    const float* Wih  = (const float*)d_in[4];
    const float* Whh  = (const float*)d_in[5];
    const float* bih  = (const float*)d_in[6];
    const float* bhh  = (const float*)d_in[7];
    float* out = (float*)d_out;

    lstm_init_kernel<<<64, 256>>>(h0);
    lstm_pipeline_kernel<<<L_ * NBLK, THREADS>>>(
        x, c0, Wih0, Wih, Whh, bih, bhh, out);
}

// round 5
// speedup vs baseline: 2.1979x; 1.2833x over previous
#include <cuda_runtime.h>
#include <math.h>

typedef unsigned long long u64;

// Problem constants
#define B_  10
#define T_  2048
#define I_  128
#define H_  256
#define L_  6
#define G4  (4 * H_)      // 1024 gate rows per layer

// Kernel config
#define NBLK     24        // blocks per layer (6*24 = 144 <= 148 SMs, co-resident)
#define THREADS  448
#define ROWS_MAX 44        // 4 * ceil(256/24)
#define JC_MAX   11
#define KC       64        // k-chunk per thread (16 float4 registers)
#define NKC_MAX  8         // 512 / 64
#define PS       9         // psum stride (conflict-free padding)
#define KSTRIDE  520       // vbuf row stride (floats)

// Scratch (device globals: allocation-free contract)
__device__ float g_hseq[(size_t)L_ * (T_ + 1) * B_ * H_];
__device__ int   g_prog[L_ * NBLK * 32];   // per-block progress, 128B padded

__global__ void lstm_init_kernel(const float* __restrict__ h0) {
    int tid = blockIdx.x * blockDim.x + threadIdx.x;
    if (tid < L_ * B_ * H_) {
        int l = tid / (B_ * H_);
        int rem = tid - l * (B_ * H_);
        g_hseq[((size_t)l * (T_ + 1)) * B_ * H_ + rem] = h0[tid];
    }
    if (tid < L_ * NBLK * 32) {
        g_prog[tid] = 0;
    }
}

__device__ __forceinline__ float tanh_approx(float x) {
    float y;
    asm("tanh.approx.f32 %0, %1;" : "=f"(y) : "f"(x));
    return y;
}

__global__ void __launch_bounds__(THREADS, 1)
lstm_pipeline_kernel(const float* __restrict__ x,
                     const float* __restrict__ c0,
                     const float* __restrict__ Wih0,
                     const float* __restrict__ Wih,   // [L-1][4H][H]
                     const float* __restrict__ Whh,   // [L][4H][H]
                     const float* __restrict__ bih,   // [L][4H]
                     const float* __restrict__ bhh,   // [L][4H]
                     float* __restrict__ out)         // [L][B][H]
{
    __shared__ float vbuf[B_ * KSTRIDE];               // [input | h_prev]
    __shared__ float psum[ROWS_MAX * B_ * PS];         // partials [r][b][kc], padded
    __shared__ float acts[ROWS_MAX * B_];              // activated gates
    __shared__ float csm[JC_MAX * B_];
    __shared__ float bsm[ROWS_MAX];

    const int l     = blockIdx.x / NBLK;
    const int p     = blockIdx.x % NBLK;
    const int jbase = (p * H_) / NBLK;
    const int jend  = ((p + 1) * H_) / NBLK;
    const int jc    = jend - jbase;     // 10 or 11
    const int rows  = 4 * jc;           // gate rows owned by this block
    const int KIN   = (l == 0) ? I_ : H_;
    const int KTOT  = KIN + H_;
    const int nkc   = KTOT / KC;        // 6 or 8
    const int tid   = threadIdx.x;

    // ---- GEMM task: thread = (kc, r); r fastest so warps share kc (v broadcast)
    const int rr = tid % ROWS_MAX;
    const int kc = tid / ROWS_MAX;
    const bool gemm_active = (rr < rows) && (kc < nkc);

    // ---- load this thread's 64 weights into registers as packed f32x2 pairs ----
    u64 wlo[KC / 4], whi[KC / 4];
    if (gemm_active) {
        const int gate = rr / jc;
        const int jl   = rr - gate * jc;
        const int g    = gate * H_ + jbase + jl;
        const int k0   = kc * KC;
        const float* wp;
        if (k0 < KIN) {
            wp = (l == 0) ? (Wih0 + (size_t)g * I_ + k0)
                          : (Wih + ((size_t)(l - 1) * G4 + g) * H_ + k0);
        } else {
            wp = Whh + ((size_t)l * G4 + g) * H_ + (k0 - KIN);
        }
        const ulonglong2* src = (const ulonglong2*)wp;
        #pragma unroll
        for (int i = 0; i < KC / 4; i++) {
            ulonglong2 w = src[i];
            wlo[i] = w.x;
            whi[i] = w.y;
        }
    } else {
        #pragma unroll
        for (int i = 0; i < KC / 4; i++) { wlo[i] = 0ULL; whi[i] = 0ULL; }
    }

    // ---- biases, initial cell state ----
    for (int r = tid; r < rows; r += THREADS) {
        int gate = r / jc;
        int jl   = r - gate * jc;
        int g    = gate * H_ + jbase + jl;
        bsm[r] = bih[l * G4 + g] + bhh[l * G4 + g];
    }
    for (int e = tid; e < jc * B_; e += THREADS) {
        int jl = e / B_;
        int b  = e - jl * B_;
        csm[e] = c0[((size_t)l * B_ + b) * H_ + jbase + jl];
    }
    __syncthreads();

    for (int t = 0; t < T_; t++) {
        // ---- wait: two dependency sets, one flag per lane, acquire loads ----
        if (tid < 32) {
            if (tid < NBLK) {
                const int* f = &g_prog[(l * NBLK + tid) * 32];
                int v;
                do {
                    asm volatile("ld.acquire.gpu.global.b32 %0, [%1];"
                                 : "=r"(v) : "l"(f));
                } while (v < t);
            }
        } else if (tid < 64) {
            if (l > 0 && tid - 32 < NBLK) {
                const int* f = &g_prog[((l - 1) * NBLK + (tid - 32)) * 32];
                int v;
                do {
                    asm volatile("ld.acquire.gpu.global.b32 %0, [%1];"
                                 : "=r"(v) : "l"(f));
                } while (v < t + 1);
            }
        }
        __syncthreads();

        // ---- build v = [input | h_prev] in smem ----
        {
            const float4* hp = (const float4*)(g_hseq +
                ((size_t)(l * (T_ + 1) + t)) * B_ * H_);
            for (int e = tid; e < B_ * (H_ / 4); e += THREADS) {
                int b  = e / (H_ / 4);
                int k4 = e - b * (H_ / 4);
                ((float4*)(vbuf + b * KSTRIDE + KIN))[k4] = hp[b * (H_ / 4) + k4];
            }
            if (l == 0) {
                const float4* xp = (const float4*)x;
                for (int e = tid; e < B_ * (I_ / 4); e += THREADS) {
                    int b  = e / (I_ / 4);
                    int k4 = e - b * (I_ / 4);
                    ((float4*)(vbuf + b * KSTRIDE))[k4] =
                        xp[((size_t)b * T_ + t) * (I_ / 4) + k4];
                }
            } else {
                const float4* ip = (const float4*)(g_hseq +
                    ((size_t)((l - 1) * (T_ + 1) + t + 1)) * B_ * H_);
                for (int e = tid; e < B_ * (H_ / 4); e += THREADS) {
                    int b  = e / (H_ / 4);
                    int k4 = e - b * (H_ / 4);
                    ((float4*)(vbuf + b * KSTRIDE))[k4] = ip[b * (H_ / 4) + k4];
                }
            }
        }
        __syncthreads();

        // ---- GEMM partials: packed f32x2 FMA, weights in regs, v broadcast ----
        if (gemm_active) {
            u64 acc[B_];
            #pragma unroll
            for (int b = 0; b < B_; b++) acc[b] = 0ULL;
            const float* vb0 = vbuf + kc * KC;
            #pragma unroll
            for (int k4 = 0; k4 < KC / 4; k4++) {
                const u64 w0 = wlo[k4];
                const u64 w1 = whi[k4];
                #pragma unroll
                for (int b = 0; b < B_; b++) {
                    const ulonglong2 v = *(const ulonglong2*)(vb0 + b * KSTRIDE + k4 * 4);
                    asm("fma.rn.f32x2 %0, %1, %2, %0;" : "+l"(acc[b]) : "l"(w0), "l"(v.x));
                    asm("fma.rn.f32x2 %0, %1, %2, %0;" : "+l"(acc[b]) : "l"(w1), "l"(v.y));
                }
            }
            float* po = psum + (rr * B_) * PS + kc;
            #pragma unroll
            for (int b = 0; b < B_; b++) {
                float xlo, xhi;
                asm("mov.b64 {%0, %1}, %2;" : "=f"(xlo), "=f"(xhi) : "l"(acc[b]));
                po[b * PS] = xlo + xhi;
            }
        }
        __syncthreads();

        // ---- activation phase: 440 threads, one (r,b) each ----
        if (tid < rows * B_) {
            const int r = tid / B_;
            const int b = tid - r * B_;
            const float* pp = psum + (r * B_ + b) * PS;
            float s = bsm[r];
            #pragma unroll
            for (int k = 0; k < NKC_MAX; k++) {
                if (k < nkc) s += pp[k];
            }
            const int gate = r / jc;
            float tv, av;
            if (gate == 2) {            // g gate: tanh
                av = tanh_approx(s);
            } else {                    // i, f, o gates: sigmoid
                tv = tanh_approx(0.5f * s);
                av = fmaf(0.5f, tv, 0.5f);
            }
            acts[r * B_ + b] = av;
        }
        __syncthreads();

        // ---- cell update + publish h slice (110 threads) ----
        float* hout = g_hseq + ((size_t)(l * (T_ + 1) + t + 1)) * B_ * H_;
        if (tid < jc * B_) {
            const int jl = tid / B_;
            const int b  = tid - jl * B_;
            float ig = acts[(0 * jc + jl) * B_ + b];
            float fg = acts[(1 * jc + jl) * B_ + b];
            float gg = acts[(2 * jc + jl) * B_ + b];
            float og = acts[(3 * jc + jl) * B_ + b];
            float c  = fmaf(fg, csm[tid], ig * gg);
            csm[tid] = c;
            hout[(size_t)b * H_ + jbase + jl] = og * tanh_approx(c);
        }
        __syncthreads();
        if (tid == 0) {
            asm volatile("st.release.gpu.global.b32 [%0], %1;"
                         :: "l"(&g_prog[(l * NBLK + p) * 32]), "r"(t + 1));
        }
    }

    // ---- final cell states -> out[L][B][H] ----
    if (tid < jc * B_) {
        int jl = tid / B_;
        int b  = tid - jl * B_;
        out[((size_t)l * B_ + b) * H_ + jbase + jl] = csm[tid];
    }
}

extern "C" void kernel_launch(void* const* d_in, const int* in_sizes, int n_in,
                              void* d_out, int out_size) {
    const float* x    = (const float*)d_in[0];
    const float* h0   = (const float*)d_in[1];
    const float* c0   = (const float*)d_in[2];
    const float* Wih0 = (const float*)d_in[3];
    const float* Wih  = (const float*)d_in[4];
    const float* Whh  = (const float*)d_in[5];
    const float* bih  = (const float*)d_in[6];
    const float* bhh  = (const float*)d_in[7];
    float* out = (float*)d_out;

    lstm_init_kernel<<<64, 256>>>(h0);
    lstm_pipeline_kernel<<<L_ * NBLK, THREADS>>>(
        x, c0, Wih0, Wih, Whh, bih, bhh, out);
}

// round 6
// speedup vs baseline: 2.2176x; 1.0090x over previous
#include <cuda_runtime.h>
#include <math.h>

typedef unsigned long long u64;

// Problem constants
#define B_  10
#define T_  2048
#define I_  128
#define H_  256
#define L_  6
#define G4  (4 * H_)      // 1024 gate rows per layer

// Kernel config
#define NBLK     24        // blocks per layer (6*24 = 144 <= 148 SMs, co-resident)
#define THREADS  448
#define ROWS_MAX 44        // 4 * ceil(256/24)
#define JC_MAX   11
#define KC       64        // k-chunk per thread
#define NKC_MAX  8         // 512 / 64
#define PS       9         // psum stride (conflict-free padding)
#define KSTRIDE  520       // vbuf row stride (floats)
#define BH       5         // batch half (two GEMM passes of 5)

// Scratch (device globals: allocation-free contract)
__device__ float g_hseq[(size_t)L_ * (T_ + 1) * B_ * H_];
__device__ int   g_prog[L_ * NBLK * 32];   // per-block progress, 128B padded

__global__ void lstm_init_kernel(const float* __restrict__ h0) {
    int tid = blockIdx.x * blockDim.x + threadIdx.x;
    if (tid < L_ * B_ * H_) {
        int l = tid / (B_ * H_);
        int rem = tid - l * (B_ * H_);
        g_hseq[((size_t)l * (T_ + 1)) * B_ * H_ + rem] = h0[tid];
    }
    if (tid < L_ * NBLK * 32) {
        g_prog[tid] = 0;
    }
}

__device__ __forceinline__ float tanh_approx(float x) {
    float y;
    asm("tanh.approx.f32 %0, %1;" : "=f"(y) : "f"(x));
    return y;
}

__global__ void __launch_bounds__(THREADS, 1)
lstm_pipeline_kernel(const float* __restrict__ x,
                     const float* __restrict__ c0,
                     const float* __restrict__ Wih0,
                     const float* __restrict__ Wih,   // [L-1][4H][H]
                     const float* __restrict__ Whh,   // [L][4H][H]
                     const float* __restrict__ bih,   // [L][4H]
                     const float* __restrict__ bhh,   // [L][4H]
                     float* __restrict__ out)         // [L][B][H]
{
    __shared__ float vbuf[B_ * KSTRIDE];               // [input | h_prev]
    __shared__ float psum[ROWS_MAX * B_ * PS];         // partials [r][b][kc], padded
    __shared__ float acts[ROWS_MAX * B_];              // activated gates
    __shared__ float csm[JC_MAX * B_];
    __shared__ float bsm[ROWS_MAX];

    const int l     = blockIdx.x / NBLK;
    const int p     = blockIdx.x % NBLK;
    const int jbase = (p * H_) / NBLK;
    const int jend  = ((p + 1) * H_) / NBLK;
    const int jc    = jend - jbase;     // 10 or 11
    const int rows  = 4 * jc;           // gate rows owned by this block
    const int KIN   = (l == 0) ? I_ : H_;
    const int KTOT  = KIN + H_;
    const int nkc   = KTOT / KC;        // 6 or 8
    const int tid   = threadIdx.x;

    // ---- GEMM task: thread = (kc, r); r fastest so warps share kc (v broadcast)
    const int rr = tid % ROWS_MAX;
    const int kc = tid / ROWS_MAX;
    const bool gemm_active = (rr < rows) && (kc < nkc);

    // ---- load this thread's 64 weights into registers as packed f32x2 pairs ----
    u64 wlo[KC / 4], whi[KC / 4];
    if (gemm_active) {
        const int gate = rr / jc;
        const int jl   = rr - gate * jc;
        const int g    = gate * H_ + jbase + jl;
        const int k0   = kc * KC;
        const float* wp;
        if (k0 < KIN) {
            wp = (l == 0) ? (Wih0 + (size_t)g * I_ + k0)
                          : (Wih + ((size_t)(l - 1) * G4 + g) * H_ + k0);
        } else {
            wp = Whh + ((size_t)l * G4 + g) * H_ + (k0 - KIN);
        }
        const ulonglong2* src = (const ulonglong2*)wp;
        #pragma unroll
        for (int i = 0; i < KC / 4; i++) {
            ulonglong2 w = src[i];
            wlo[i] = w.x;
            whi[i] = w.y;
        }
    } else {
        #pragma unroll
        for (int i = 0; i < KC / 4; i++) { wlo[i] = 0ULL; whi[i] = 0ULL; }
    }

    // ---- biases, initial cell state ----
    for (int r = tid; r < rows; r += THREADS) {
        int gate = r / jc;
        int jl   = r - gate * jc;
        int g    = gate * H_ + jbase + jl;
        bsm[r] = bih[l * G4 + g] + bhh[l * G4 + g];
    }
    for (int e = tid; e < jc * B_; e += THREADS) {
        int jl = e / B_;
        int b  = e - jl * B_;
        csm[e] = c0[((size_t)l * B_ + b) * H_ + jbase + jl];
    }
    __syncthreads();

    for (int t = 0; t < T_; t++) {
        // ---- wait: two dependency sets, one flag per lane, acquire loads ----
        if (tid < 32) {
            if (tid < NBLK) {
                const int* f = &g_prog[(l * NBLK + tid) * 32];
                int v;
                do {
                    asm volatile("ld.acquire.gpu.global.b32 %0, [%1];"
                                 : "=r"(v) : "l"(f));
                } while (v < t);
            }
        } else if (tid < 64) {
            if (l > 0 && tid - 32 < NBLK) {
                const int* f = &g_prog[((l - 1) * NBLK + (tid - 32)) * 32];
                int v;
                do {
                    asm volatile("ld.acquire.gpu.global.b32 %0, [%1];"
                                 : "=r"(v) : "l"(f));
                } while (v < t + 1);
            }
        }
        __syncthreads();

        // ---- build v = [input | h_prev] in smem ----
        {
            const float4* hp = (const float4*)(g_hseq +
                ((size_t)(l * (T_ + 1) + t)) * B_ * H_);
            for (int e = tid; e < B_ * (H_ / 4); e += THREADS) {
                int b  = e / (H_ / 4);
                int k4 = e - b * (H_ / 4);
                ((float4*)(vbuf + b * KSTRIDE + KIN))[k4] = hp[b * (H_ / 4) + k4];
            }
            if (l == 0) {
                const float4* xp = (const float4*)x;
                for (int e = tid; e < B_ * (I_ / 4); e += THREADS) {
                    int b  = e / (I_ / 4);
                    int k4 = e - b * (I_ / 4);
                    ((float4*)(vbuf + b * KSTRIDE))[k4] =
                        xp[((size_t)b * T_ + t) * (I_ / 4) + k4];
                }
            } else {
                const float4* ip = (const float4*)(g_hseq +
                    ((size_t)((l - 1) * (T_ + 1) + t + 1)) * B_ * H_);
                for (int e = tid; e < B_ * (H_ / 4); e += THREADS) {
                    int b  = e / (H_ / 4);
                    int k4 = e - b * (H_ / 4);
                    ((float4*)(vbuf + b * KSTRIDE))[k4] = ip[b * (H_ / 4) + k4];
                }
            }
        }
        __syncthreads();

        // ---- GEMM partials: two passes of 5 batches (reg pressure < 128) ----
        if (gemm_active) {
            const float* vb0 = vbuf + kc * KC;
            float* po = psum + (rr * B_) * PS + kc;
            #pragma unroll
            for (int pass = 0; pass < 2; pass++) {
                u64 acc[BH];
                #pragma unroll
                for (int b = 0; b < BH; b++) acc[b] = 0ULL;
                const float* vp = vb0 + (size_t)(pass * BH) * KSTRIDE;
                #pragma unroll
                for (int k4 = 0; k4 < KC / 4; k4++) {
                    const u64 w0 = wlo[k4];
                    const u64 w1 = whi[k4];
                    #pragma unroll
                    for (int b = 0; b < BH; b++) {
                        const ulonglong2 v =
                            *(const ulonglong2*)(vp + b * KSTRIDE + k4 * 4);
                        asm("fma.rn.f32x2 %0, %1, %2, %0;"
                            : "+l"(acc[b]) : "l"(w0), "l"(v.x));
                        asm("fma.rn.f32x2 %0, %1, %2, %0;"
                            : "+l"(acc[b]) : "l"(w1), "l"(v.y));
                    }
                }
                #pragma unroll
                for (int b = 0; b < BH; b++) {
                    float xlo, xhi;
                    asm("mov.b64 {%0, %1}, %2;"
                        : "=f"(xlo), "=f"(xhi) : "l"(acc[b]));
                    po[(pass * BH + b) * PS] = xlo + xhi;
                }
            }
        }
        __syncthreads();

        // ---- activation phase: 440 threads, one (r,b) each ----
        if (tid < rows * B_) {
            const int r = tid / B_;
            const int b = tid - r * B_;
            const float* pp = psum + (r * B_ + b) * PS;
            float s = bsm[r];
            #pragma unroll
            for (int k = 0; k < NKC_MAX; k++) {
                if (k < nkc) s += pp[k];
            }
            const int gate = r / jc;
            float av;
            if (gate == 2) {            // g gate: tanh
                av = tanh_approx(s);
            } else {                    // i, f, o gates: sigmoid
                av = fmaf(0.5f, tanh_approx(0.5f * s), 0.5f);
            }
            acts[r * B_ + b] = av;
        }
        __syncthreads();

        // ---- cell update + publish h slice (110 threads) ----
        float* hout = g_hseq + ((size_t)(l * (T_ + 1) + t + 1)) * B_ * H_;
        if (tid < jc * B_) {
            const int jl = tid / B_;
            const int b  = tid - jl * B_;
            float ig = acts[(0 * jc + jl) * B_ + b];
            float fg = acts[(1 * jc + jl) * B_ + b];
            float gg = acts[(2 * jc + jl) * B_ + b];
            float og = acts[(3 * jc + jl) * B_ + b];
            float c  = fmaf(fg, csm[tid], ig * gg);
            csm[tid] = c;
            hout[(size_t)b * H_ + jbase + jl] = og * tanh_approx(c);
        }
        __syncthreads();
        if (tid == 0) {
            asm volatile("st.release.gpu.global.b32 [%0], %1;"
                         :: "l"(&g_prog[(l * NBLK + p) * 32]), "r"(t + 1));
        }
    }

    // ---- final cell states -> out[L][B][H] ----
    if (tid < jc * B_) {
        int jl = tid / B_;
        int b  = tid - jl * B_;
        out[((size_t)l * B_ + b) * H_ + jbase + jl] = csm[tid];
    }
}

extern "C" void kernel_launch(void* const* d_in, const int* in_sizes, int n_in,
                              void* d_out, int out_size) {
    const float* x    = (const float*)d_in[0];
    const float* h0   = (const float*)d_in[1];
    const float* c0   = (const float*)d_in[2];
    const float* Wih0 = (const float*)d_in[3];
    const float* Wih  = (const float*)d_in[4];
    const float* Whh  = (const float*)d_in[5];
    const float* bih  = (const float*)d_in[6];
    const float* bhh  = (const float*)d_in[7];
    float* out = (float*)d_out;

    lstm_init_kernel<<<64, 256>>>(h0);
    lstm_pipeline_kernel<<<L_ * NBLK, THREADS>>>(
        x, c0, Wih0, Wih, Whh, bih, bhh, out);
}

// round 7
// speedup vs baseline: 2.2380x; 1.0092x over previous
#include <cuda_runtime.h>
#include <math.h>

typedef unsigned long long u64;

// Problem constants
#define B_  10
#define T_  2048
#define I_  128
#define H_  256
#define L_  6
#define G4  (4 * H_)      // 1024 gate rows per layer

// Kernel config
#define NBLK     24        // blocks per layer (6*24 = 144 <= 148 SMs, co-resident)
#define THREADS  448
#define ROWS_MAX 44        // 4 * ceil(256/24)
#define JC_MAX   11
#define KC       64        // k-chunk per thread
#define NKC_MAX  8         // 512 / 64
#define PS       9         // psum stride (conflict-free padding)
#define KSTRIDE  520       // vbuf row stride (floats)
#define BH       5         // batch half (two GEMM passes of 5)

// Scratch (device globals: allocation-free contract)
__device__ float g_hseq[(size_t)L_ * (T_ + 1) * B_ * H_];
__device__ int   g_prog[L_ * NBLK * 32];   // per-block progress, 128B padded

__global__ void lstm_init_kernel(const float* __restrict__ h0) {
    int tid = blockIdx.x * blockDim.x + threadIdx.x;
    if (tid < L_ * B_ * H_) {
        int l = tid / (B_ * H_);
        int rem = tid - l * (B_ * H_);
        g_hseq[((size_t)l * (T_ + 1)) * B_ * H_ + rem] = h0[tid];
    }
    if (tid < L_ * NBLK * 32) {
        g_prog[tid] = 0;
    }
}

__device__ __forceinline__ float tanh_approx(float x) {
    float y;
    asm("tanh.approx.f32 %0, %1;" : "=f"(y) : "f"(x));
    return y;
}

__global__ void __launch_bounds__(THREADS, 1)
lstm_pipeline_kernel(const float* __restrict__ x,
                     const float* __restrict__ c0,
                     const float* __restrict__ Wih0,
                     const float* __restrict__ Wih,   // [L-1][4H][H]
                     const float* __restrict__ Whh,   // [L][4H][H]
                     const float* __restrict__ bih,   // [L][4H]
                     const float* __restrict__ bhh,   // [L][4H]
                     float* __restrict__ out)         // [L][B][H]
{
    __shared__ float vbuf[B_ * KSTRIDE];               // [input | h_prev]
    __shared__ float psum[ROWS_MAX * B_ * PS];         // partials [r][b][kc], padded
    __shared__ float csm[JC_MAX * B_];
    __shared__ float bsm[ROWS_MAX];

    const int l     = blockIdx.x / NBLK;
    const int p     = blockIdx.x % NBLK;
    const int jbase = (p * H_) / NBLK;
    const int jend  = ((p + 1) * H_) / NBLK;
    const int jc    = jend - jbase;     // 10 or 11
    const int rows  = 4 * jc;           // gate rows owned by this block
    const int KIN   = (l == 0) ? I_ : H_;
    const int KTOT  = KIN + H_;
    const int nkc   = KTOT / KC;        // 6 or 8
    const int tid   = threadIdx.x;
    const int jcB   = jc * B_;

    // ---- GEMM task: thread = (kc, r); r fastest so warps share kc (v broadcast)
    const int rr = tid % ROWS_MAX;
    const int kc = tid / ROWS_MAX;
    const bool gemm_active = (rr < rows) && (kc < nkc);

    // ---- load this thread's 64 weights into registers as packed f32x2 pairs ----
    u64 wlo[KC / 4], whi[KC / 4];
    if (gemm_active) {
        const int gate = rr / jc;
        const int jl   = rr - gate * jc;
        const int g    = gate * H_ + jbase + jl;
        const int k0   = kc * KC;
        const float* wp;
        if (k0 < KIN) {
            wp = (l == 0) ? (Wih0 + (size_t)g * I_ + k0)
                          : (Wih + ((size_t)(l - 1) * G4 + g) * H_ + k0);
        } else {
            wp = Whh + ((size_t)l * G4 + g) * H_ + (k0 - KIN);
        }
        const ulonglong2* src = (const ulonglong2*)wp;
        #pragma unroll
        for (int i = 0; i < KC / 4; i++) {
            ulonglong2 w = src[i];
            wlo[i] = w.x;
            whi[i] = w.y;
        }
    } else {
        #pragma unroll
        for (int i = 0; i < KC / 4; i++) { wlo[i] = 0ULL; whi[i] = 0ULL; }
    }

    // ---- biases, initial cell state, psum zero-fill (unused kc slots stay 0) ----
    for (int r = tid; r < rows; r += THREADS) {
        int gate = r / jc;
        int jl   = r - gate * jc;
        int g    = gate * H_ + jbase + jl;
        bsm[r] = bih[l * G4 + g] + bhh[l * G4 + g];
    }
    for (int e = tid; e < jcB; e += THREADS) {
        int jl = e / B_;
        int b  = e - jl * B_;
        csm[e] = c0[((size_t)l * B_ + b) * H_ + jbase + jl];
    }
    for (int e = tid; e < ROWS_MAX * B_ * PS; e += THREADS) {
        psum[e] = 0.f;
    }
    __syncthreads();

    for (int t = 0; t < T_; t++) {
        // ---- phase A: x-part prefetch (l=0, no dependency) + flag polls ----
        if (l == 0) {
            const float4* xp = (const float4*)x;
            for (int e = tid; e < B_ * (I_ / 4); e += THREADS) {
                int b  = e / (I_ / 4);
                int k4 = e - b * (I_ / 4);
                ((float4*)(vbuf + b * KSTRIDE))[k4] =
                    xp[((size_t)b * T_ + t) * (I_ / 4) + k4];
            }
        }
        if (tid < 32) {
            if (tid < NBLK) {
                const int* f = &g_prog[(l * NBLK + tid) * 32];
                int v;
                do {
                    asm volatile("ld.acquire.gpu.global.b32 %0, [%1];"
                                 : "=r"(v) : "l"(f));
                } while (v < t);
            }
        } else if (tid < 64) {
            if (l > 0 && tid - 32 < NBLK) {
                const int* f = &g_prog[((l - 1) * NBLK + (tid - 32)) * 32];
                int v;
                do {
                    asm volatile("ld.acquire.gpu.global.b32 %0, [%1];"
                                 : "=r"(v) : "l"(f));
                } while (v < t + 1);
            }
        }
        __syncthreads();   // S1

        // ---- phase B: h-dependent parts of v ----
        {
            const float4* hp = (const float4*)(g_hseq +
                ((size_t)(l * (T_ + 1) + t)) * B_ * H_);
            for (int e = tid; e < B_ * (H_ / 4); e += THREADS) {
                int b  = e / (H_ / 4);
                int k4 = e - b * (H_ / 4);
                ((float4*)(vbuf + b * KSTRIDE + KIN))[k4] = hp[b * (H_ / 4) + k4];
            }
            if (l > 0) {
                const float4* ip = (const float4*)(g_hseq +
                    ((size_t)((l - 1) * (T_ + 1) + t + 1)) * B_ * H_);
                for (int e = tid; e < B_ * (H_ / 4); e += THREADS) {
                    int b  = e / (H_ / 4);
                    int k4 = e - b * (H_ / 4);
                    ((float4*)(vbuf + b * KSTRIDE))[k4] = ip[b * (H_ / 4) + k4];
                }
            }
        }
        __syncthreads();   // S2

        // ---- GEMM partials: two passes of 5 batches, packed f32x2 FMA ----
        if (gemm_active) {
            const float* vb0 = vbuf + kc * KC;
            float* po = psum + (rr * B_) * PS + kc;
            #pragma unroll
            for (int pass = 0; pass < 2; pass++) {
                u64 acc[BH];
                #pragma unroll
                for (int b = 0; b < BH; b++) acc[b] = 0ULL;
                const float* vp = vb0 + (size_t)(pass * BH) * KSTRIDE;
                #pragma unroll
                for (int k4 = 0; k4 < KC / 4; k4++) {
                    const u64 w0 = wlo[k4];
                    const u64 w1 = whi[k4];
                    #pragma unroll
                    for (int b = 0; b < BH; b++) {
                        const ulonglong2 v =
                            *(const ulonglong2*)(vp + b * KSTRIDE + k4 * 4);
                        asm("fma.rn.f32x2 %0, %1, %2, %0;"
                            : "+l"(acc[b]) : "l"(w0), "l"(v.x));
                        asm("fma.rn.f32x2 %0, %1, %2, %0;"
                            : "+l"(acc[b]) : "l"(w1), "l"(v.y));
                    }
                }
                #pragma unroll
                for (int b = 0; b < BH; b++) {
                    float xlo, xhi;
                    asm("mov.b64 {%0, %1}, %2;"
                        : "=f"(xlo), "=f"(xhi) : "l"(acc[b]));
                    po[(pass * BH + b) * PS] = xlo + xhi;
                }
            }
        }
        __syncthreads();   // S3

        // ---- fused reduce + activations + cell update (warps 0-3 only) ----
        if (tid < 128) {
            if (tid < jcB) {
                const int jl = tid / B_;
                const int b  = tid - jl * B_;
                float gs[4];
                #pragma unroll
                for (int gate = 0; gate < 4; gate++) {
                    const int r = gate * jc + jl;
                    const float* pp = psum + (r * B_ + b) * PS;
                    float s0 = pp[0] + pp[1];
                    float s1 = pp[2] + pp[3];
                    float s2 = pp[4] + pp[5];
                    float s3 = pp[6] + pp[7];
                    gs[gate] = bsm[r] + ((s0 + s1) + (s2 + s3));
                }
                float ig = fmaf(0.5f, tanh_approx(0.5f * gs[0]), 0.5f);
                float fg = fmaf(0.5f, tanh_approx(0.5f * gs[1]), 0.5f);
                float gg = tanh_approx(gs[2]);
                float og = fmaf(0.5f, tanh_approx(0.5f * gs[3]), 0.5f);
                float c  = fmaf(fg, csm[tid], ig * gg);
                csm[tid] = c;
                float* hout = g_hseq + ((size_t)(l * (T_ + 1) + t + 1)) * B_ * H_;
                hout[(size_t)b * H_ + jbase + jl] = og * tanh_approx(c);
            }
            asm volatile("bar.sync 1, 128;" ::: "memory");
            if (tid == 0) {
                asm volatile("st.release.gpu.global.b32 [%0], %1;"
                             :: "l"(&g_prog[(l * NBLK + p) * 32]), "r"(t + 1));
            }
        }
        // warps 4-13 bypass to the next iteration (S1 re-syncs everyone)
    }

    // ---- final cell states -> out[L][B][H] (same threads that wrote csm) ----
    if (tid < jcB) {
        int jl = tid / B_;
        int b  = tid - jl * B_;
        out[((size_t)l * B_ + b) * H_ + jbase + jl] = csm[tid];
    }
}

extern "C" void kernel_launch(void* const* d_in, const int* in_sizes, int n_in,
                              void* d_out, int out_size) {
    const float* x    = (const float*)d_in[0];
    const float* h0   = (const float*)d_in[1];
    const float* c0   = (const float*)d_in[2];
    const float* Wih0 = (const float*)d_in[3];
    const float* Wih  = (const float*)d_in[4];
    const float* Whh  = (const float*)d_in[5];
    const float* bih  = (const float*)d_in[6];
    const float* bhh  = (const float*)d_in[7];
    float* out = (float*)d_out;

    lstm_init_kernel<<<64, 256>>>(h0);
    lstm_pipeline_kernel<<<L_ * NBLK, THREADS>>>(
        x, c0, Wih0, Wih, Whh, bih, bhh, out);
}

// round 8
// speedup vs baseline: 2.5877x; 1.1562x over previous
#include <cuda_runtime.h>
#include <math.h>

typedef unsigned long long u64;

// Problem constants
#define B_  10
#define T_  2048
#define I_  128
#define H_  256
#define L_  6
#define G4  (4 * H_)      // 1024 gate rows per layer

// Kernel config
#define NBLK     24        // blocks per layer (6*24 = 144 <= 148 SMs, co-resident)
#define THREADS  448
#define ROWS_MAX 44        // 4 * ceil(256/24)
#define JC_MAX   11
#define KC       64        // k-chunk per thread
#define NKC_MAX  8         // 512 / 64
#define PS       9         // psum stride (conflict-free padding)
#define KSTRIDE  520       // vbuf row stride (floats)
#define BH       5         // batch half (two GEMM passes of 5)
#define CELL0    192       // first cell thread (warps 6-9: tids 192..319)

// Scratch (device globals: allocation-free contract)
__device__ float g_hseq[(size_t)L_ * (T_ + 1) * B_ * H_];
__device__ int   g_prog[L_ * NBLK * 32];   // per-block progress, 128B padded

__global__ void lstm_init_kernel(const float* __restrict__ h0) {
    int tid = blockIdx.x * blockDim.x + threadIdx.x;
    if (tid < L_ * B_ * H_) {
        int l = tid / (B_ * H_);
        int rem = tid - l * (B_ * H_);
        g_hseq[((size_t)l * (T_ + 1)) * B_ * H_ + rem] = h0[tid];
    }
    if (tid < L_ * NBLK * 32) {
        g_prog[tid] = 0;
    }
}

__device__ __forceinline__ float tanh_approx(float x) {
    float y;
    asm("tanh.approx.f32 %0, %1;" : "=f"(y) : "f"(x));
    return y;
}

__device__ __forceinline__ int ld_acq(const int* p) {
    int v;
    asm volatile("ld.acquire.gpu.global.b32 %0, [%1];" : "=r"(v) : "l"(p));
    return v;
}

__global__ void __launch_bounds__(THREADS, 1)
lstm_pipeline_kernel(const float* __restrict__ x,
                     const float* __restrict__ c0,
                     const float* __restrict__ Wih0,
                     const float* __restrict__ Wih,   // [L-1][4H][H]
                     const float* __restrict__ Whh,   // [L][4H][H]
                     const float* __restrict__ bih,   // [L][4H]
                     const float* __restrict__ bhh,   // [L][4H]
                     float* __restrict__ out)         // [L][B][H]
{
    __shared__ float vbuf[B_ * KSTRIDE];               // [input | h_prev]
    __shared__ float psum[ROWS_MAX * B_ * PS];         // partials [r][b][kc], padded
    __shared__ float csm[JC_MAX * B_];
    __shared__ float bsm[ROWS_MAX];

    const int l     = blockIdx.x / NBLK;
    const int p     = blockIdx.x % NBLK;
    const int jbase = (p * H_) / NBLK;
    const int jend  = ((p + 1) * H_) / NBLK;
    const int jc    = jend - jbase;     // 10 or 11
    const int rows  = 4 * jc;           // gate rows owned by this block
    const int KIN   = (l == 0) ? I_ : H_;
    const int KTOT  = KIN + H_;
    const int nkc   = KTOT / KC;        // 6 or 8
    const int nkcx  = KIN / KC;         // input-half k-chunks: 2 or 4
    const int tid   = threadIdx.x;
    const int wid   = tid >> 5;
    const int jcB   = jc * B_;

    // ---- GEMM task: thread = (kc, r); r fastest so warps share kc (v broadcast)
    const int rr = tid % ROWS_MAX;
    const int kc = tid / ROWS_MAX;
    const bool gemm_active = (rr < rows) && (kc < nkc);
    const bool is_input_kc = gemm_active && (kc < nkcx);
    const bool is_rec_kc   = gemm_active && (kc >= nkcx);

    // ---- load this thread's 64 weights into registers as packed f32x2 pairs ----
    u64 wlo[KC / 4], whi[KC / 4];
    if (gemm_active) {
        const int gate = rr / jc;
        const int jl   = rr - gate * jc;
        const int g    = gate * H_ + jbase + jl;
        const int k0   = kc * KC;
        const float* wp;
        if (k0 < KIN) {
            wp = (l == 0) ? (Wih0 + (size_t)g * I_ + k0)
                          : (Wih + ((size_t)(l - 1) * G4 + g) * H_ + k0);
        } else {
            wp = Whh + ((size_t)l * G4 + g) * H_ + (k0 - KIN);
        }
        const ulonglong2* src = (const ulonglong2*)wp;
        #pragma unroll
        for (int i = 0; i < KC / 4; i++) {
            ulonglong2 w = src[i];
            wlo[i] = w.x;
            whi[i] = w.y;
        }
    } else {
        #pragma unroll
        for (int i = 0; i < KC / 4; i++) { wlo[i] = 0ULL; whi[i] = 0ULL; }
    }

    // ---- biases, initial cell state, psum zero-fill ----
    for (int r = tid; r < rows; r += THREADS) {
        int gate = r / jc;
        int jl   = r - gate * jc;
        int g    = gate * H_ + jbase + jl;
        bsm[r] = bih[l * G4 + g] + bhh[l * G4 + g];
    }
    for (int e = tid; e < jcB; e += THREADS) {
        int jl = e / B_;
        int b  = e - jl * B_;
        csm[e] = c0[((size_t)l * B_ + b) * H_ + jbase + jl];
    }
    for (int e = tid; e < ROWS_MAX * B_ * PS; e += THREADS) {
        psum[e] = 0.f;
    }
    // pre-loop: verify lower-layer flags for t=0 (prog[l-1] >= 1)
    if (l > 0 && wid == 12 && (tid & 31) < NBLK) {
        const int* f = &g_prog[((l - 1) * NBLK + (tid & 31)) * 32];
        while (ld_acq(f) < 1) { }
    }
    __syncthreads();

    // pre-loop P0: input v-build for t=0 (own flags >= 0 trivially true)
    if (tid < CELL0) {
        if (l == 0) {
            const float4* xp = (const float4*)x;
            for (int e = tid; e < B_ * (I_ / 4); e += CELL0) {
                int b  = e / (I_ / 4);
                int k4 = e - b * (I_ / 4);
                ((float4*)(vbuf + b * KSTRIDE))[k4] =
                    xp[((size_t)b * T_) * (I_ / 4) + k4];
            }
        } else {
            const float4* ip = (const float4*)(g_hseq +
                ((size_t)((l - 1) * (T_ + 1) + 1)) * B_ * H_);
            for (int e = tid; e < B_ * (H_ / 4); e += CELL0) {
                int b  = e / (H_ / 4);
                int k4 = e - b * (H_ / 4);
                ((float4*)(vbuf + b * KSTRIDE))[k4] = ip[b * (H_ / 4) + k4];
            }
        }
    }

    for (int t = 0; t < T_; t++) {
        __syncthreads();   // S1: input-v ready; own flags(t) verified

        // ---- P1: GEMM_x (input-kc threads) || recurrent v-build (tids 192-383) ----
        if (is_input_kc) {
            const float* vb0 = vbuf + kc * KC;
            float* po = psum + (rr * B_) * PS + kc;
            #pragma unroll
            for (int pass = 0; pass < 2; pass++) {
                u64 acc[BH];
                #pragma unroll
                for (int b = 0; b < BH; b++) acc[b] = 0ULL;
                const float* vp = vb0 + (size_t)(pass * BH) * KSTRIDE;
                #pragma unroll
                for (int k4 = 0; k4 < KC / 4; k4++) {
                    const u64 w0 = wlo[k4];
                    const u64 w1 = whi[k4];
                    #pragma unroll
                    for (int b = 0; b < BH; b++) {
                        const ulonglong2 v =
                            *(const ulonglong2*)(vp + b * KSTRIDE + k4 * 4);
                        asm("fma.rn.f32x2 %0, %1, %2, %0;"
                            : "+l"(acc[b]) : "l"(w0), "l"(v.x));
                        asm("fma.rn.f32x2 %0, %1, %2, %0;"
                            : "+l"(acc[b]) : "l"(w1), "l"(v.y));
                    }
                }
                #pragma unroll
                for (int b = 0; b < BH; b++) {
                    float xlo, xhi;
                    asm("mov.b64 {%0, %1}, %2;"
                        : "=f"(xlo), "=f"(xhi) : "l"(acc[b]));
                    po[(pass * BH + b) * PS] = xlo + xhi;
                }
            }
        } else if (tid >= 192 && tid < 384) {
            // recurrent v-build: LDG hseq[l][t] -> vbuf[KIN..]
            const float4* hp = (const float4*)(g_hseq +
                ((size_t)(l * (T_ + 1) + t)) * B_ * H_);
            for (int e = tid - 192; e < B_ * (H_ / 4); e += 192) {
                int b  = e / (H_ / 4);
                int k4 = e - b * (H_ / 4);
                ((float4*)(vbuf + b * KSTRIDE + KIN))[k4] = hp[b * (H_ / 4) + k4];
            }
        }
        __syncthreads();   // S2

        // ---- P2: GEMM_h (recurrent-kc threads) || warp12 pre-poll lower(t+2) ----
        if (is_rec_kc) {
            const float* vb0 = vbuf + kc * KC;
            float* po = psum + (rr * B_) * PS + kc;
            #pragma unroll
            for (int pass = 0; pass < 2; pass++) {
                u64 acc[BH];
                #pragma unroll
                for (int b = 0; b < BH; b++) acc[b] = 0ULL;
                const float* vp = vb0 + (size_t)(pass * BH) * KSTRIDE;
                #pragma unroll
                for (int k4 = 0; k4 < KC / 4; k4++) {
                    const u64 w0 = wlo[k4];
                    const u64 w1 = whi[k4];
                    #pragma unroll
                    for (int b = 0; b < BH; b++) {
                        const ulonglong2 v =
                            *(const ulonglong2*)(vp + b * KSTRIDE + k4 * 4);
                        asm("fma.rn.f32x2 %0, %1, %2, %0;"
                            : "+l"(acc[b]) : "l"(w0), "l"(v.x));
                        asm("fma.rn.f32x2 %0, %1, %2, %0;"
                            : "+l"(acc[b]) : "l"(w1), "l"(v.y));
                    }
                }
                #pragma unroll
                for (int b = 0; b < BH; b++) {
                    float xlo, xhi;
                    asm("mov.b64 {%0, %1}, %2;"
                        : "=f"(xlo), "=f"(xhi) : "l"(acc[b]));
                    po[(pass * BH + b) * PS] = xlo + xhi;
                }
            }
        } else if (wid == 12 && l > 0 && t + 2 <= T_ && (tid & 31) < NBLK) {
            const int* f = &g_prog[((l - 1) * NBLK + (tid & 31)) * 32];
            while (ld_acq(f) < t + 2) { }
        }
        __syncthreads();   // S3

        // ---- P3: cell (warps 6-9) || input v-build(t+1) (warps 0-5) || own poll (warp13)
        if (tid >= CELL0 && tid < CELL0 + 128) {
            const int e = tid - CELL0;
            if (e < jcB) {
                const int jl = e / B_;
                const int b  = e - jl * B_;
                float gs[4];
                #pragma unroll
                for (int gate = 0; gate < 4; gate++) {
                    const int r = gate * jc + jl;
                    const float* pp = psum + (r * B_ + b) * PS;
                    float s0 = pp[0] + pp[1];
                    float s1 = pp[2] + pp[3];
                    float s2 = pp[4] + pp[5];
                    float s3 = pp[6] + pp[7];
                    gs[gate] = bsm[r] + ((s0 + s1) + (s2 + s3));
                }
                float ig = fmaf(0.5f, tanh_approx(0.5f * gs[0]), 0.5f);
                float fg = fmaf(0.5f, tanh_approx(0.5f * gs[1]), 0.5f);
                float gg = tanh_approx(gs[2]);
                float og = fmaf(0.5f, tanh_approx(0.5f * gs[3]), 0.5f);
                float c  = fmaf(fg, csm[e], ig * gg);
                csm[e] = c;
                float* hout = g_hseq + ((size_t)(l * (T_ + 1) + t + 1)) * B_ * H_;
                hout[(size_t)b * H_ + jbase + jl] = og * tanh_approx(c);
            }
            asm volatile("bar.sync 2, 128;" ::: "memory");
            if (tid == CELL0) {
                asm volatile("st.release.gpu.global.b32 [%0], %1;"
                             :: "l"(&g_prog[(l * NBLK + p) * 32]), "r"(t + 1));
            }
        } else if (tid < CELL0) {
            // input v-build for t+1 (lower flags t+2 verified in P2)
            if (t + 1 < T_) {
                if (l == 0) {
                    const float4* xp = (const float4*)x;
                    for (int e = tid; e < B_ * (I_ / 4); e += CELL0) {
                        int b  = e / (I_ / 4);
                        int k4 = e - b * (I_ / 4);
                        ((float4*)(vbuf + b * KSTRIDE))[k4] =
                            xp[((size_t)b * T_ + t + 1) * (I_ / 4) + k4];
                    }
                } else {
                    const float4* ip = (const float4*)(g_hseq +
                        ((size_t)((l - 1) * (T_ + 1) + t + 2)) * B_ * H_);
                    for (int e = tid; e < B_ * (H_ / 4); e += CELL0) {
                        int b  = e / (H_ / 4);
                        int k4 = e - b * (H_ / 4);
                        ((float4*)(vbuf + b * KSTRIDE))[k4] = ip[b * (H_ / 4) + k4];
                    }
                }
            }
        } else if (wid == 13) {
            // poll own-layer flags for t+1
            if (t + 1 < T_ && (tid & 31) < NBLK) {
                const int* f = &g_prog[(l * NBLK + (tid & 31)) * 32];
                while (ld_acq(f) < t + 1) { }
            }
        }
        // next S1 closes the pipeline stage
    }

    // ---- final cell states -> out[L][B][H] (cell threads own csm) ----
    if (tid >= CELL0 && tid < CELL0 + jcB) {
        int e  = tid - CELL0;
        int jl = e / B_;
        int b  = e - jl * B_;
        out[((size_t)l * B_ + b) * H_ + jbase + jl] = csm[e];
    }
}

extern "C" void kernel_launch(void* const* d_in, const int* in_sizes, int n_in,
                              void* d_out, int out_size) {
    const float* x    = (const float*)d_in[0];
    const float* h0   = (const float*)d_in[1];
    const float* c0   = (const float*)d_in[2];
    const float* Wih0 = (const float*)d_in[3];
    const float* Wih  = (const float*)d_in[4];
    const float* Whh  = (const float*)d_in[5];
    const float* bih  = (const float*)d_in[6];
    const float* bhh  = (const float*)d_in[7];
    float* out = (float*)d_out;

    lstm_init_kernel<<<64, 256>>>(h0);
    lstm_pipeline_kernel<<<L_ * NBLK, THREADS>>>(
        x, c0, Wih0, Wih, Whh, bih, bhh, out);
}